// round 5
// baseline (speedup 1.0000x reference)
#include <cuda_runtime.h>
#include <math_constants.h>

// Problem geometry
#define NSRC 16384
#define NTAR 16384
#define NSPLIT 128                      // source splits
#define SRCB  (NSRC / NSPLIT)           // 128 sources per split
#define NTHREADS 256
#define TPT 4                           // targets per thread (2 packed pairs)
#define NPAIR (TPT / 2)                 // 2
#define TB (NTAR / (NTHREADS * TPT))    // 16 target blocks
#define TAR_PER_BLOCK (NTHREADS * TPT)  // 1024
#define RED_BLOCKS 64
#define RED_THREADS 256

// Scratch (allocation-free rule: __device__ globals)
__device__ float g_vmax[NSPLIT * NTAR];     // per-split per-target max of (t.s - 0.5||s||^2)
__device__ float g_partial[RED_BLOCKS];     // per-block partial sums
__device__ int   g_ctr = 0;                 // last-block counter (reset after use)

// ---- packed f32x2 helpers (FFMA2 only reachable via PTX) --------------------
__device__ __forceinline__ unsigned long long pk2(float a, float b) {
    unsigned long long r;
    asm("mov.b64 %0, {%1, %2};" : "=l"(r) : "f"(a), "f"(b));
    return r;
}
__device__ __forceinline__ unsigned long long ffma2(unsigned long long a,
                                                    unsigned long long b,
                                                    unsigned long long c) {
    unsigned long long d;
    asm("fma.rn.f32x2 %0, %1, %2, %3;" : "=l"(d) : "l"(a), "l"(b), "l"(c));
    return d;
}
__device__ __forceinline__ void upk2(unsigned long long v, float& lo, float& hi) {
    asm("mov.b64 {%0, %1}, %2;" : "=f"(lo), "=f"(hi) : "l"(v));
}

// ---------------------------------------------------------------------------
// Main pairwise pass. grid = (TB, NSPLIT) = 2048 blocks, 256 threads.
// smem holds the split's sources as duplicated packed 64-bit lanes:
//   s_xy[j] = { (x,x), (y,y) }   s_zw[j] = { (z,z), (w,w) },  w = -0.5||s||^2
// LDS.128 lands the operands directly in aligned 64-bit register pairs.
// Inner loop per source: 2 LDS.128 + 6 FFMA2 + 4 FMNMX (serves 4 targets).
// ---------------------------------------------------------------------------
__global__ __launch_bounds__(NTHREADS) void nn_main_kernel(const float* __restrict__ src,
                                                           const float* __restrict__ tar) {
    __shared__ ulonglong2 s_xy[SRCB];
    __shared__ ulonglong2 s_zw[SRCB];

    const int tb    = blockIdx.x;
    const int split = blockIdx.y;

    // In-block source prep (SRCB=128 sources, threads 0..127)
    if (threadIdx.x < SRCB) {
        int g = split * SRCB + threadIdx.x;
        float x = src[3 * g + 0];
        float y = src[3 * g + 1];
        float z = src[3 * g + 2];
        float w = -0.5f * (x * x + y * y + z * z);
        s_xy[threadIdx.x] = make_ulonglong2(pk2(x, x), pk2(y, y));
        s_zw[threadIdx.x] = make_ulonglong2(pk2(z, z), pk2(w, w));
    }
    __syncthreads();

    const int t0 = tb * TAR_PER_BLOCK + threadIdx.x;

    unsigned long long txp[NPAIR], typ[NPAIR], tzp[NPAIR];
    float m[TPT];
#pragma unroll
    for (int p = 0; p < NPAIR; p++) {
        int ta = t0 + (2 * p) * NTHREADS;
        int tc = t0 + (2 * p + 1) * NTHREADS;
        txp[p] = pk2(tar[3 * ta + 0], tar[3 * tc + 0]);
        typ[p] = pk2(tar[3 * ta + 1], tar[3 * tc + 1]);
        tzp[p] = pk2(tar[3 * ta + 2], tar[3 * tc + 2]);
        m[2 * p]     = -CUDART_INF_F;
        m[2 * p + 1] = -CUDART_INF_F;
    }

#pragma unroll 2
    for (int j = 0; j < SRCB; j++) {
        ulonglong2 xy = s_xy[j];             // (xx, yy)
        ulonglong2 zw = s_zw[j];             // (zz, ww)
#pragma unroll
        for (int p = 0; p < NPAIR; p++) {
            unsigned long long v = ffma2(tzp[p], zw.x, zw.y);   // t.z*z + w
            v = ffma2(typ[p], xy.y, v);
            v = ffma2(txp[p], xy.x, v);
            float lo, hi;
            upk2(v, lo, hi);
            m[2 * p]     = fmaxf(m[2 * p], lo);
            m[2 * p + 1] = fmaxf(m[2 * p + 1], hi);
        }
    }

#pragma unroll
    for (int k = 0; k < TPT; k++)
        g_vmax[split * NTAR + t0 + k * NTHREADS] = m[k];
}

// ---------------------------------------------------------------------------
// Reduce: combine splits, add 0.5||t||^2, block-reduce; the LAST block to
// finish additionally sums all per-block partials in FIXED index order
// (bitwise deterministic) and resets the counter for graph replay.
// ---------------------------------------------------------------------------
__global__ __launch_bounds__(RED_THREADS) void nn_reduce_kernel(const float* __restrict__ tar,
                                                                float* __restrict__ out) {
    __shared__ float red[RED_THREADS];
    __shared__ bool  amLast;
    const int t = blockIdx.x * RED_THREADS + threadIdx.x;

    float vm = -CUDART_INF_F;
#pragma unroll 8
    for (int s = 0; s < NSPLIT; s++)
        vm = fmaxf(vm, g_vmax[s * NTAR + t]);

    float x = tar[3 * t + 0];
    float y = tar[3 * t + 1];
    float z = tar[3 * t + 2];
    // 0.5||t||^2 - max_s(t.s - 0.5||s||^2) == 0.5*min_s ||t - s||^2
    float c = fmaf(0.5f * x, x, fmaf(0.5f * y, y, fmaf(0.5f * z, z, -vm)));

    red[threadIdx.x] = c;
    __syncthreads();
#pragma unroll
    for (int stride = RED_THREADS / 2; stride > 0; stride >>= 1) {
        if (threadIdx.x < stride)
            red[threadIdx.x] += red[threadIdx.x + stride];
        __syncthreads();
    }

    if (threadIdx.x == 0) {
        g_partial[blockIdx.x] = red[0];
        __threadfence();
        int old = atomicAdd(&g_ctr, 1);
        amLast = (old == RED_BLOCKS - 1);
    }
    __syncthreads();

    if (amLast && threadIdx.x == 0) {
        float s = 0.0f;
#pragma unroll
        for (int i = 0; i < RED_BLOCKS; i++)     // fixed order -> deterministic
            s += g_partial[i];
        out[0] = s;
        g_ctr = 0;                               // reset for next graph replay
        __threadfence();
    }
}

extern "C" void kernel_launch(void* const* d_in, const int* in_sizes, int n_in,
                              void* d_out, int out_size) {
    const float* src = (const float*)d_in[0];   // src_V [16384,3]
    const float* tar = (const float*)d_in[1];   // tar_V [16384,3]
    float* out = (float*)d_out;

    dim3 grid(TB, NSPLIT);
    nn_main_kernel<<<grid, NTHREADS>>>(src, tar);
    nn_reduce_kernel<<<RED_BLOCKS, RED_THREADS>>>(tar, out);
}

// round 6
// speedup vs baseline: 1.2229x; 1.2229x over previous
#include <cuda_runtime.h>
#include <math_constants.h>

// Problem geometry
#define NSRC 16384
#define NTAR 16384
#define NSPLIT 128                      // source splits
#define SRCB  (NSRC / NSPLIT)           // 128 sources per split
#define SPAIRS (SRCB / 2)               // 64 packed source pairs per split
#define NTHREADS 256
#define TPT 4                           // targets per thread
#define TB (NTAR / (NTHREADS * TPT))    // 16 target blocks
#define TAR_PER_BLOCK (NTHREADS * TPT)  // 1024
#define NBLOCKS (TB * NSPLIT)           // 2048

// Scratch (allocation-free rule: __device__ globals)
// g_vmax_u: monotone-mapped per-target max. Zero-init: mapped(f) > 0 for every
// real f (mapped(-inf)=0x007FFFFF), so 0 acts as "-infinity". Consumer resets
// entries to 0 for the next graph replay.
__device__ unsigned int g_vmax_u[NTAR];
__device__ int g_ctr = 0;               // last-block counter (reset after use)

// ---- packed f32x2 helpers (FFMA2 only reachable via PTX) --------------------
__device__ __forceinline__ unsigned long long pk2(float a, float b) {
    unsigned long long r;
    asm("mov.b64 %0, {%1, %2};" : "=l"(r) : "f"(a), "f"(b));
    return r;
}
__device__ __forceinline__ unsigned long long ffma2(unsigned long long a,
                                                    unsigned long long b,
                                                    unsigned long long c) {
    unsigned long long d;
    asm("fma.rn.f32x2 %0, %1, %2, %3;" : "=l"(d) : "l"(a), "l"(b), "l"(c));
    return d;
}
__device__ __forceinline__ void upk2(unsigned long long v, float& lo, float& hi) {
    asm("mov.b64 {%0, %1}, %2;" : "=f"(lo), "=f"(hi) : "l"(v));
}

// Order-preserving float <-> uint mapping (for exact, deterministic atomicMax)
__device__ __forceinline__ unsigned int fmap(float f) {
    unsigned int u = __float_as_uint(f);
    return (u & 0x80000000u) ? ~u : (u | 0x80000000u);
}
__device__ __forceinline__ float funmap(unsigned int mu) {
    return (mu & 0x80000000u) ? __uint_as_float(mu ^ 0x80000000u)
                              : __uint_as_float(~mu);
}

// ---------------------------------------------------------------------------
// Single fused kernel. grid = (TB, NSPLIT) = 2048 blocks x 256 threads.
//
// smem: sources packed BY PAIR into f32x2 lanes (no duplication):
//   s_q0[j] = { (ax,bx), (ay,by) }   s_q1[j] = { (az,bz), (aw,bw) }
// with w = -0.5*||s||^2. Targets are broadcast-duplicated in registers.
// Inner loop per j: 2 LDS.128 + 12 FFMA2 + 8 FMNMX, serving 2 src x 4 tgt.
//
// Results land via deterministic atomicMax into g_vmax_u; the LAST block
// (counter) computes the final loss, resets state for graph replay.
// ---------------------------------------------------------------------------
__global__ __launch_bounds__(NTHREADS) void nn_fused_kernel(const float* __restrict__ src,
                                                            const float* __restrict__ tar,
                                                            float* __restrict__ out) {
    __shared__ ulonglong2 s_q0[SPAIRS];
    __shared__ ulonglong2 s_q1[SPAIRS];
    __shared__ bool amLast;
    __shared__ float red[NTHREADS];

    const int tb    = blockIdx.x;
    const int split = blockIdx.y;

    // In-block source prep: thread i < 64 handles source pair (2i, 2i+1)
    if (threadIdx.x < SPAIRS) {
        int g = split * SRCB + 2 * threadIdx.x;
        float ax = src[3 * g + 0], ay = src[3 * g + 1], az = src[3 * g + 2];
        float bx = src[3 * g + 3], by = src[3 * g + 4], bz = src[3 * g + 5];
        float aw = -0.5f * (ax * ax + ay * ay + az * az);
        float bw = -0.5f * (bx * bx + by * by + bz * bz);
        s_q0[threadIdx.x] = make_ulonglong2(pk2(ax, bx), pk2(ay, by));
        s_q1[threadIdx.x] = make_ulonglong2(pk2(az, bz), pk2(aw, bw));
    }
    __syncthreads();

    const int t0 = tb * TAR_PER_BLOCK + threadIdx.x;

    // Broadcast-duplicated packed targets
    unsigned long long txp[TPT], typ[TPT], tzp[TPT];
    float m[TPT];
#pragma unroll
    for (int k = 0; k < TPT; k++) {
        int t = t0 + k * NTHREADS;
        float x = tar[3 * t + 0], y = tar[3 * t + 1], z = tar[3 * t + 2];
        txp[k] = pk2(x, x);
        typ[k] = pk2(y, y);
        tzp[k] = pk2(z, z);
        m[k] = -CUDART_INF_F;
    }

#pragma unroll 4
    for (int j = 0; j < SPAIRS; j++) {
        ulonglong2 q0 = s_q0[j];            // ((ax,bx),(ay,by))
        ulonglong2 q1 = s_q1[j];            // ((az,bz),(aw,bw))
#pragma unroll
        for (int k = 0; k < TPT; k++) {
            // v = (t.sa - 0.5||sa||^2 , t.sb - 0.5||sb||^2)
            unsigned long long v = ffma2(tzp[k], q1.x, q1.y);
            v = ffma2(typ[k], q0.y, v);
            v = ffma2(txp[k], q0.x, v);
            float lo, hi;
            upk2(v, lo, hi);                // register aliasing: 0 SASS
            m[k] = fmaxf(m[k], fmaxf(lo, hi));
        }
    }

    // Deterministic cross-split max combine
#pragma unroll
    for (int k = 0; k < TPT; k++)
        atomicMax(&g_vmax_u[t0 + k * NTHREADS], fmap(m[k]));

    // ---- last-block final reduction ----
    __threadfence();
    if (threadIdx.x == 0) {
        int old = atomicAdd(&g_ctr, 1);
        amLast = (old == NBLOCKS - 1);
    }
    __syncthreads();
    if (!amLast) return;

    __threadfence();                        // acquire: see all atomicMax results
    float acc = 0.0f;
    for (int t = threadIdx.x; t < NTAR; t += NTHREADS) {   // fixed per-thread order
        unsigned int mu = g_vmax_u[t];
        g_vmax_u[t] = 0;                    // reset for next graph replay
        float vm = funmap(mu);
        float x = tar[3 * t + 0], y = tar[3 * t + 1], z = tar[3 * t + 2];
        // 0.5||t||^2 - max_s(t.s - 0.5||s||^2) == 0.5*min_s ||t-s||^2
        acc += fmaf(0.5f * x, x, fmaf(0.5f * y, y, fmaf(0.5f * z, z, -vm)));
    }
    red[threadIdx.x] = acc;
    __syncthreads();
#pragma unroll
    for (int stride = NTHREADS / 2; stride > 0; stride >>= 1) {
        if (threadIdx.x < stride)
            red[threadIdx.x] += red[threadIdx.x + stride];
        __syncthreads();
    }
    if (threadIdx.x == 0) {
        out[0] = red[0];
        g_ctr = 0;                          // reset for next graph replay
        __threadfence();
    }
}

extern "C" void kernel_launch(void* const* d_in, const int* in_sizes, int n_in,
                              void* d_out, int out_size) {
    const float* src = (const float*)d_in[0];   // src_V [16384,3]
    const float* tar = (const float*)d_in[1];   // tar_V [16384,3]
    float* out = (float*)d_out;

    dim3 grid(TB, NSPLIT);
    nn_fused_kernel<<<grid, NTHREADS>>>(src, tar, out);
}